// round 13
// baseline (speedup 1.0000x reference)
#include <cuda_runtime.h>
#include <cuda_fp16.h>

// Factorized ray-marching: x@W1+b1 = p1 + alpha*u.
// R13: R12 structure (ONE row per warp in phase B, block = 512 thr / 16 rows)
// with the warp reduction done via redux.sync.add.s32 on a 2^16 fixed-point
// value (redux.f32 does not exist on sm_103). Phase A: 16 warps x (16 rows x
// 2 n-tiles) HMMA, A-fragments from smem (conflict-free LDS.32).

#define D_DIM 128
#define H_DIM 256
#define KT    8
#define NT    32
#define UPAD  264            // halves per u row
#define RPAD  136            // halves per staged r row

__device__ __half2 g_p1h2[H_DIM / 2];
__device__ __half2 g_w2h2[H_DIM / 2];
__device__ uint2   g_Bfrag[KT * NT * 32];   // 64 KB: W1 in HMMA B-fragment layout

static __device__ __forceinline__ float tanh_fast(float x) {
    float y; asm("tanh.approx.f32 %0, %1;" : "=f"(y) : "f"(x)); return y;
}
static __device__ __forceinline__ __half2 tanh2_fast(__half2 x) {
    __half2 y;
    asm("tanh.approx.f16x2 %0, %1;" : "=r"(*(unsigned*)&y) : "r"(*(unsigned*)&x));
    return y;
}
// warp sum via s32 redux on 2^16 fixed point (f32 redux unsupported on sm_103)
static __device__ __forceinline__ float warp_sum_fx(float v) {
    int iv = __float2int_rn(v * 65536.f);
    int s;
    asm volatile("redux.sync.add.s32 %0, %1, 0xffffffff;" : "=r"(s) : "r"(iv));
    return (float)s * (1.f / 65536.f);
}
static __device__ __forceinline__ unsigned h2bits(__half2 v) { return *(unsigned*)&v; }
static __device__ __forceinline__ void mma16816(float& c0, float& c1, float& c2, float& c3,
                                                unsigned a0, unsigned a1, unsigned a2, unsigned a3,
                                                unsigned b0, unsigned b1) {
    asm volatile("mma.sync.aligned.m16n8k16.row.col.f32.f16.f16.f32 "
                 "{%0,%1,%2,%3}, {%4,%5,%6,%7}, {%8,%9}, {%0,%1,%2,%3};"
                 : "+f"(c0), "+f"(c1), "+f"(c2), "+f"(c3)
                 : "r"(a0), "r"(a1), "r"(a2), "r"(a3), "r"(b0), "r"(b1));
}

// prep (grid 9, block 1024): block 0 -> p1 (4-way d-split reduction) + half
// copies; blocks 1..8 -> W1 B-fragment packing.
__global__ __launch_bounds__(1024)
void prep_kernel(const float* __restrict__ pivot,
                 const float* __restrict__ W1,
                 const float* __restrict__ b1,
                 const float* __restrict__ w2) {
    if (blockIdx.x == 0) {
        __shared__ float red[4][H_DIM];
        __shared__ float sp1[H_DIM];
        const int j  = threadIdx.x & 255;
        const int dg = threadIdx.x >> 8;
        float s = 0.f;
        const int d0 = dg * 32;
#pragma unroll 8
        for (int d = d0; d < d0 + 32; ++d)
            s = fmaf(pivot[d], W1[(size_t)d * H_DIM + j], s);
        red[dg][j] = s;
        __syncthreads();
        if (dg == 0)
            sp1[j] = red[0][j] + red[1][j] + red[2][j] + red[3][j] + b1[j];
        __syncthreads();
        if (threadIdx.x < H_DIM / 2) {
            g_p1h2[threadIdx.x] = __floats2half2_rn(sp1[2 * threadIdx.x],
                                                    sp1[2 * threadIdx.x + 1]);
            g_w2h2[threadIdx.x] = __floats2half2_rn(w2[2 * threadIdx.x],
                                                    w2[2 * threadIdx.x + 1]);
        }
    } else {
        const int e = (blockIdx.x - 1) * 1024 + threadIdx.x;   // 0..8191
        const int tile = e >> 5;
        const int lane = e & 31;
        const int kt = tile / NT;
        const int nt = tile % NT;
        const int g = lane >> 2, t4 = lane & 3;
        const int k0 = kt * 16 + t4 * 2;
        const int col = nt * 8 + g;
        __half2 b0v = __floats2half2_rn(W1[(size_t)k0 * H_DIM + col],
                                        W1[(size_t)(k0 + 1) * H_DIM + col]);
        __half2 b1v = __floats2half2_rn(W1[(size_t)(k0 + 8) * H_DIM + col],
                                        W1[(size_t)(k0 + 9) * H_DIM + col]);
        g_Bfrag[tile * 32 + lane] = make_uint2(h2bits(b0v), h2bits(b1v));
    }
}

// ============== fused main kernel: block = 16 rows, 16 warps ==============
__global__ __launch_bounds__(512, 3)
void main_kernel(const float* __restrict__ r,
                 const float* __restrict__ s_in,
                 const float* __restrict__ pivot,
                 const float* __restrict__ b2,
                 const int* __restrict__ n_iter_ptr,
                 float* __restrict__ out,
                 int B) {
    __shared__ __half u_sh[16][UPAD];     // 8.25 KB
    __shared__ __half r_sh[16][RPAD];     // 4.25 KB: normalized r rows (half)
    __shared__ float  inv_sh[16];

    const int lane = threadIdx.x & 31;
    const int wib  = threadIdx.x >> 5;          // 0..15
    const int base_row = blockIdx.x * 16;

    // ---------- Stage 0: warp wib loads row wib, normalizes, stores half ----------
    {
        const int row = base_row + wib;
        float4 v = (row < B) ? ((const float4*)(r + (size_t)row * D_DIM))[lane]
                             : make_float4(0.f, 0.f, 0.f, 0.f);
        float ss = fmaf(v.x, v.x, fmaf(v.y, v.y, fmaf(v.z, v.z, v.w * v.w)));
#pragma unroll
        for (int o = 16; o; o >>= 1) ss += __shfl_xor_sync(0xffffffffu, ss, o);
        const float inv = rsqrtf(ss);
        if (lane == 0) inv_sh[wib] = inv;
        *(__half2*)&r_sh[wib][lane * 4]     = __floats2half2_rn(v.x * inv, v.y * inv);
        *(__half2*)&r_sh[wib][lane * 4 + 2] = __floats2half2_rn(v.z * inv, v.w * inv);
    }
    __syncthreads();

    // ---------- Phase A: HMMA. warp = 16 rows x 16 cols (2 n-tiles) ----------
    {
        const int ntg = wib * 2;
        const int g4 = lane >> 2, t4 = lane & 3;

        float acc[2][4];
#pragma unroll
        for (int t = 0; t < 2; ++t)
#pragma unroll
            for (int q = 0; q < 4; ++q) acc[t][q] = 0.f;

#pragma unroll
        for (int kt = 0; kt < KT; ++kt) {
            const int cbase = kt * 16 + t4 * 2;
            const unsigned a0 = *(const unsigned*)&r_sh[g4][cbase];
            const unsigned a1 = *(const unsigned*)&r_sh[g4 + 8][cbase];
            const unsigned a2 = *(const unsigned*)&r_sh[g4][cbase + 8];
            const unsigned a3 = *(const unsigned*)&r_sh[g4 + 8][cbase + 8];

            const uint2* bb = g_Bfrag + (size_t)(kt * NT + ntg) * 32 + lane;
            uint2 bf0 = __ldg(bb);
            uint2 bf1 = __ldg(bb + 32);
            mma16816(acc[0][0], acc[0][1], acc[0][2], acc[0][3],
                     a0, a1, a2, a3, bf0.x, bf0.y);
            mma16816(acc[1][0], acc[1][1], acc[1][2], acc[1][3],
                     a0, a1, a2, a3, bf1.x, bf1.y);
        }

#pragma unroll
        for (int t = 0; t < 2; ++t) {
            const int col = (ntg + t) * 8 + t4 * 2;
            *(__half2*)&u_sh[g4][col]     = __floats2half2_rn(acc[t][0], acc[t][1]);
            *(__half2*)&u_sh[g4 + 8][col] = __floats2half2_rn(acc[t][2], acc[t][3]);
        }
    }
    __syncthreads();

    // ---------- Phase B: 20-step recurrence, ONE row per warp ----------
    const int row = base_row + wib;
    if (row >= B) return;

    // lane owns 8 hidden units: 8*lane .. 8*lane+7 (one uint4 each)
    __half2 u2[4], p12[4], w22[4];
    {
        uint4 uu = *(const uint4*)(&u_sh[wib][lane * 8]);
        uint4 aa = __ldg((const uint4*)g_p1h2 + lane);
        uint4 bb = __ldg((const uint4*)g_w2h2 + lane);
        u2[0] = *(__half2*)&uu.x; u2[1] = *(__half2*)&uu.y;
        u2[2] = *(__half2*)&uu.z; u2[3] = *(__half2*)&uu.w;
        p12[0] = *(__half2*)&aa.x; p12[1] = *(__half2*)&aa.y;
        p12[2] = *(__half2*)&aa.z; p12[3] = *(__half2*)&aa.w;
        w22[0] = *(__half2*)&bb.x; w22[1] = *(__half2*)&bb.y;
        w22[2] = *(__half2*)&bb.z; w22[3] = *(__half2*)&bb.w;
    }

    const float b2v = b2[0];
    const int n = n_iter_ptr ? *n_iter_ptr : 20;
    const __half2 h2z = __floats2half2_rn(0.f, 0.f);

    float alpha = 0.f;
    for (int it = 0; it < n; ++it) {
        const __half2 a2h = __float2half2_rn(alpha);
        __half2 za = __hfma2(a2h, u2[0], p12[0]);
        __half2 zb = __hfma2(a2h, u2[1], p12[1]);
        __half2 zc = __hfma2(a2h, u2[2], p12[2]);
        __half2 zd = __hfma2(a2h, u2[3], p12[3]);
        __half2 acc2a = __hfma2(tanh2_fast(za), w22[0], h2z);
        __half2 acc2b = __hfma2(tanh2_fast(zb), w22[1], h2z);
        acc2a = __hfma2(tanh2_fast(zc), w22[2], acc2a);
        acc2b = __hfma2(tanh2_fast(zd), w22[3], acc2b);
        __half2 acc2 = __hadd2(acc2a, acc2b);
        float accf = __low2float(acc2) + __high2float(acc2);
        accf = warp_sum_fx(accf);
        alpha += 0.05f * (1.0f + tanh_fast(accf + b2v));
    }

    // tail: output (lane owns dims 4*lane .. 4*lane+3)
    const float inv_norm = inv_sh[wib];
    const float sv = s_in[row];
    const float sig = 1.0f / (1.0f + __expf(-sv));
    const float fscale = sig * alpha * inv_norm;

    float4 rv = ((const float4*)(r + (size_t)row * D_DIM))[lane];
    float4 pv = ((const float4*)pivot)[lane];
    float4 o;
    o.x = fmaf(fscale, rv.x, pv.x);
    o.y = fmaf(fscale, rv.y, pv.y);
    o.z = fmaf(fscale, rv.z, pv.z);
    o.w = fmaf(fscale, rv.w, pv.w);
    ((float4*)(out + (size_t)row * D_DIM))[lane] = o;
}

extern "C" void kernel_launch(void* const* d_in, const int* in_sizes, int n_in,
                              void* d_out, int out_size) {
    const float* r     = (const float*)d_in[0];   // [B,128]
    const float* s     = (const float*)d_in[1];   // [B,1]
    const float* pivot = (const float*)d_in[2];   // [128]
    const float* W1    = (const float*)d_in[3];   // [128,256]
    const float* b1    = (const float*)d_in[4];   // [256]
    const float* w2    = (const float*)d_in[5];   // [256]
    const float* b2    = (const float*)d_in[6];   // [1]
    const int* n_iter  = (n_in > 7) ? (const int*)d_in[7] : nullptr;
    float* out = (float*)d_out;

    const int B = in_sizes[0] / D_DIM;

    prep_kernel<<<9, 1024>>>(pivot, W1, b1, w2);

    const int blocks = (B + 15) / 16;
    main_kernel<<<blocks, 512>>>(r, s, pivot, b2, n_iter, out, B);
}

// round 14
// speedup vs baseline: 1.0947x; 1.0947x over previous
#include <cuda_runtime.h>
#include <cuda_fp16.h>

// Factorized ray-marching: x@W1+b1 = p1 + alpha*u.
// R14: R11 + dead-zone filling. Warp carries 4 rows as TWO independent
// 16-lane-group pairs; their per-iteration chains interleave so pair B's
// tanh work hides pair A's shfl-reduction latency. Block = 32 rows / 8 warps.
// Phase A: warp = 16 rows x 64 cols HMMA (2 passes), A-frags from smem.

#define D_DIM 128
#define H_DIM 256
#define KT    8
#define NT    32
#define UPAD  264            // halves per u row
#define RPAD  136            // halves per staged r row

__device__ __half2 g_p1h2[H_DIM / 2];
__device__ __half2 g_w2h2[H_DIM / 2];
__device__ uint2   g_Bfrag[KT * NT * 32];   // 64 KB: W1 in HMMA B-fragment layout

static __device__ __forceinline__ float tanh_fast(float x) {
    float y; asm("tanh.approx.f32 %0, %1;" : "=f"(y) : "f"(x)); return y;
}
static __device__ __forceinline__ __half2 tanh2_fast(__half2 x) {
    __half2 y;
    asm("tanh.approx.f16x2 %0, %1;" : "=r"(*(unsigned*)&y) : "r"(*(unsigned*)&x));
    return y;
}
static __device__ __forceinline__ unsigned h2bits(__half2 v) { return *(unsigned*)&v; }
static __device__ __forceinline__ void mma16816(float& c0, float& c1, float& c2, float& c3,
                                                unsigned a0, unsigned a1, unsigned a2, unsigned a3,
                                                unsigned b0, unsigned b1) {
    asm volatile("mma.sync.aligned.m16n8k16.row.col.f32.f16.f16.f32 "
                 "{%0,%1,%2,%3}, {%4,%5,%6,%7}, {%8,%9}, {%0,%1,%2,%3};"
                 : "+f"(c0), "+f"(c1), "+f"(c2), "+f"(c3)
                 : "r"(a0), "r"(a1), "r"(a2), "r"(a3), "r"(b0), "r"(b1));
}

// prep (grid 9, block 1024): block 0 -> p1 (4-way d-split reduction) + half
// copies; blocks 1..8 -> W1 B-fragment packing.
__global__ __launch_bounds__(1024)
void prep_kernel(const float* __restrict__ pivot,
                 const float* __restrict__ W1,
                 const float* __restrict__ b1,
                 const float* __restrict__ w2) {
    if (blockIdx.x == 0) {
        __shared__ float red[4][H_DIM];
        __shared__ float sp1[H_DIM];
        const int j  = threadIdx.x & 255;
        const int dg = threadIdx.x >> 8;
        float s = 0.f;
        const int d0 = dg * 32;
#pragma unroll 8
        for (int d = d0; d < d0 + 32; ++d)
            s = fmaf(pivot[d], W1[(size_t)d * H_DIM + j], s);
        red[dg][j] = s;
        __syncthreads();
        if (dg == 0)
            sp1[j] = red[0][j] + red[1][j] + red[2][j] + red[3][j] + b1[j];
        __syncthreads();
        if (threadIdx.x < H_DIM / 2) {
            g_p1h2[threadIdx.x] = __floats2half2_rn(sp1[2 * threadIdx.x],
                                                    sp1[2 * threadIdx.x + 1]);
            g_w2h2[threadIdx.x] = __floats2half2_rn(w2[2 * threadIdx.x],
                                                    w2[2 * threadIdx.x + 1]);
        }
    } else {
        const int e = (blockIdx.x - 1) * 1024 + threadIdx.x;   // 0..8191
        const int tile = e >> 5;
        const int lane = e & 31;
        const int kt = tile / NT;
        const int nt = tile % NT;
        const int g = lane >> 2, t4 = lane & 3;
        const int k0 = kt * 16 + t4 * 2;
        const int col = nt * 8 + g;
        __half2 b0v = __floats2half2_rn(W1[(size_t)k0 * H_DIM + col],
                                        W1[(size_t)(k0 + 1) * H_DIM + col]);
        __half2 b1v = __floats2half2_rn(W1[(size_t)(k0 + 8) * H_DIM + col],
                                        W1[(size_t)(k0 + 9) * H_DIM + col]);
        g_Bfrag[tile * 32 + lane] = make_uint2(h2bits(b0v), h2bits(b1v));
    }
}

// ============== fused main kernel: block = 32 rows, 8 warps ==============
__global__ __launch_bounds__(256, 5)
void main_kernel(const float* __restrict__ r,
                 const float* __restrict__ s_in,
                 const float* __restrict__ pivot,
                 const float* __restrict__ b2,
                 const int* __restrict__ n_iter_ptr,
                 float* __restrict__ out,
                 int B) {
    __shared__ __half u_sh[32][UPAD];     // 16.5 KB
    __shared__ __half r_sh[32][RPAD];     // 8.5 KB: normalized r rows (half)
    __shared__ float  inv_sh[32];

    const int lane = threadIdx.x & 31;
    const int wib  = threadIdx.x >> 5;          // 0..7
    const int base_row = blockIdx.x * 32;

    // ---------- Stage 0: each warp stages 4 rows (coalesced, normalized) ----------
#pragma unroll
    for (int p = 0; p < 4; ++p) {
        const int lrow = wib + p * 8;
        const int row = base_row + lrow;
        float4 v = (row < B) ? ((const float4*)(r + (size_t)row * D_DIM))[lane]
                             : make_float4(0.f, 0.f, 0.f, 0.f);
        float ss = fmaf(v.x, v.x, fmaf(v.y, v.y, fmaf(v.z, v.z, v.w * v.w)));
#pragma unroll
        for (int o = 16; o; o >>= 1) ss += __shfl_xor_sync(0xffffffffu, ss, o);
        const float inv = rsqrtf(ss);
        if (lane == 0) inv_sh[lrow] = inv;
        *(__half2*)&r_sh[lrow][lane * 4]     = __floats2half2_rn(v.x * inv, v.y * inv);
        *(__half2*)&r_sh[lrow][lane * 4 + 2] = __floats2half2_rn(v.z * inv, v.w * inv);
    }
    __syncthreads();

    // ---------- Phase A: HMMA. warp = 16 rows x 64 cols (8 n-tiles, 2 passes) ----------
    {
        const int rowg = (wib >> 2) * 16;          // 0 or 16
        const int ntg  = (wib & 3) * 8;            // first of 8 n-tiles
        const int g4 = lane >> 2, t4 = lane & 3;

#pragma unroll
        for (int half = 0; half < 2; ++half) {
            float acc[4][4];
#pragma unroll
            for (int t = 0; t < 4; ++t)
#pragma unroll
                for (int q = 0; q < 4; ++q) acc[t][q] = 0.f;

#pragma unroll
            for (int kt = 0; kt < KT; ++kt) {
                const int cbase = kt * 16 + t4 * 2;
                const unsigned a0 = *(const unsigned*)&r_sh[rowg + g4][cbase];
                const unsigned a1 = *(const unsigned*)&r_sh[rowg + g4 + 8][cbase];
                const unsigned a2 = *(const unsigned*)&r_sh[rowg + g4][cbase + 8];
                const unsigned a3 = *(const unsigned*)&r_sh[rowg + g4 + 8][cbase + 8];

                const uint2* bb = g_Bfrag + (size_t)(kt * NT + ntg + half * 4) * 32 + lane;
                uint2 bf[4];
#pragma unroll
                for (int t = 0; t < 4; ++t) bf[t] = __ldg(bb + t * 32);
#pragma unroll
                for (int t = 0; t < 4; ++t)
                    mma16816(acc[t][0], acc[t][1], acc[t][2], acc[t][3],
                             a0, a1, a2, a3, bf[t].x, bf[t].y);
            }
#pragma unroll
            for (int t = 0; t < 4; ++t) {
                const int col = (ntg + half * 4 + t) * 8 + t4 * 2;
                *(__half2*)&u_sh[rowg + g4][col]     = __floats2half2_rn(acc[t][0], acc[t][1]);
                *(__half2*)&u_sh[rowg + g4 + 8][col] = __floats2half2_rn(acc[t][2], acc[t][3]);
            }
        }
    }
    __syncthreads();

    // ---------- Phase B: 20 steps, 4 rows/warp = 2 interleaved 16-lane pairs ----------
    const int l16 = lane & 15;
    const int sub = lane >> 4;
    const int lrowA = wib * 4 + sub;          // pair A: block rows wib*4 + {0,1}
    const int lrowB = wib * 4 + 2 + sub;      // pair B: block rows wib*4 + {2,3}
    const int rowA = base_row + lrowA;
    const int rowB = base_row + lrowB;
    if (rowA >= B) return;

    __half2 uA[8], uB[8], p12[8], w22[8];
    {
        const uint4* upA = (const uint4*)(&u_sh[lrowA][0]) + l16 * 2;
        const uint4* upB = (const uint4*)(&u_sh[lrowB][0]) + l16 * 2;
        const uint4* pp = (const uint4*)g_p1h2 + l16 * 2;
        const uint4* wp = (const uint4*)g_w2h2 + l16 * 2;
#pragma unroll
        for (int v = 0; v < 2; ++v) {
            uint4 ua = upA[v], ub = upB[v];
            uint4 aa = __ldg(pp + v), bb = __ldg(wp + v);
            uA[v * 4 + 0] = *(__half2*)&ua.x; uA[v * 4 + 1] = *(__half2*)&ua.y;
            uA[v * 4 + 2] = *(__half2*)&ua.z; uA[v * 4 + 3] = *(__half2*)&ua.w;
            uB[v * 4 + 0] = *(__half2*)&ub.x; uB[v * 4 + 1] = *(__half2*)&ub.y;
            uB[v * 4 + 2] = *(__half2*)&ub.z; uB[v * 4 + 3] = *(__half2*)&ub.w;
            p12[v * 4 + 0] = *(__half2*)&aa.x; p12[v * 4 + 1] = *(__half2*)&aa.y;
            p12[v * 4 + 2] = *(__half2*)&aa.z; p12[v * 4 + 3] = *(__half2*)&aa.w;
            w22[v * 4 + 0] = *(__half2*)&bb.x; w22[v * 4 + 1] = *(__half2*)&bb.y;
            w22[v * 4 + 2] = *(__half2*)&bb.z; w22[v * 4 + 3] = *(__half2*)&bb.w;
        }
    }

    const float b2v = b2[0];
    const int n = n_iter_ptr ? *n_iter_ptr : 20;
    const __half2 h2z = __floats2half2_rn(0.f, 0.f);

    float alphaA = 0.f, alphaB = 0.f;
    for (int it = 0; it < n; ++it) {
        const __half2 aA = __float2half2_rn(alphaA);
        const __half2 aB = __float2half2_rn(alphaB);
        __half2 sA0 = h2z, sA1 = h2z, sB0 = h2z, sB1 = h2z;
#pragma unroll
        for (int q = 0; q < 8; q += 2) {
            __half2 zA0 = __hfma2(aA, uA[q],     p12[q]);
            __half2 zA1 = __hfma2(aA, uA[q + 1], p12[q + 1]);
            __half2 zB0 = __hfma2(aB, uB[q],     p12[q]);
            __half2 zB1 = __hfma2(aB, uB[q + 1], p12[q + 1]);
            sA0 = __hfma2(tanh2_fast(zA0), w22[q],     sA0);
            sA1 = __hfma2(tanh2_fast(zA1), w22[q + 1], sA1);
            sB0 = __hfma2(tanh2_fast(zB0), w22[q],     sB0);
            sB1 = __hfma2(tanh2_fast(zB1), w22[q + 1], sB1);
        }
        __half2 sA = __hadd2(sA0, sA1);
        __half2 sB = __hadd2(sB0, sB1);
        float fA = __low2float(sA) + __high2float(sA);
        float fB = __low2float(sB) + __high2float(sB);
        // two independent reduction chains — B's shfls overlap A's latency
        fA += __shfl_xor_sync(0xffffffffu, fA, 1);
        fB += __shfl_xor_sync(0xffffffffu, fB, 1);
        fA += __shfl_xor_sync(0xffffffffu, fA, 2);
        fB += __shfl_xor_sync(0xffffffffu, fB, 2);
        fA += __shfl_xor_sync(0xffffffffu, fA, 4);
        fB += __shfl_xor_sync(0xffffffffu, fB, 4);
        fA += __shfl_xor_sync(0xffffffffu, fA, 8);
        fB += __shfl_xor_sync(0xffffffffu, fB, 8);
        alphaA += 0.05f * (1.0f + tanh_fast(fA + b2v));
        alphaB += 0.05f * (1.0f + tanh_fast(fB + b2v));
    }

    // tail: outputs for both rows (lane owns dims 8*l16 .. 8*l16+7)
    const float4* pv4 = (const float4*)pivot + l16 * 2;
    float4 pv0 = pv4[0], pv1 = pv4[1];
#pragma unroll
    for (int pr = 0; pr < 2; ++pr) {
        const int row  = pr ? rowB : rowA;
        const int lrow = pr ? lrowB : lrowA;
        const float alpha = pr ? alphaB : alphaA;
        if (row >= B) break;
        const float sv = s_in[row];
        const float sig = 1.0f / (1.0f + __expf(-sv));
        const float fscale = sig * alpha * inv_sh[lrow];

        const float4* rv4 = (const float4*)(r + (size_t)row * D_DIM) + l16 * 2;
        float4* ov4 = (float4*)(out + (size_t)row * D_DIM) + l16 * 2;
        float4 rv = rv4[0];
        float4 o;
        o.x = fmaf(fscale, rv.x, pv0.x);
        o.y = fmaf(fscale, rv.y, pv0.y);
        o.z = fmaf(fscale, rv.z, pv0.z);
        o.w = fmaf(fscale, rv.w, pv0.w);
        ov4[0] = o;
        rv = rv4[1];
        o.x = fmaf(fscale, rv.x, pv1.x);
        o.y = fmaf(fscale, rv.y, pv1.y);
        o.z = fmaf(fscale, rv.z, pv1.z);
        o.w = fmaf(fscale, rv.w, pv1.w);
        ov4[1] = o;
    }
}

extern "C" void kernel_launch(void* const* d_in, const int* in_sizes, int n_in,
                              void* d_out, int out_size) {
    const float* r     = (const float*)d_in[0];   // [B,128]
    const float* s     = (const float*)d_in[1];   // [B,1]
    const float* pivot = (const float*)d_in[2];   // [128]
    const float* W1    = (const float*)d_in[3];   // [128,256]
    const float* b1    = (const float*)d_in[4];   // [256]
    const float* w2    = (const float*)d_in[5];   // [256]
    const float* b2    = (const float*)d_in[6];   // [1]
    const int* n_iter  = (n_in > 7) ? (const int*)d_in[7] : nullptr;
    float* out = (float*)d_out;

    const int B = in_sizes[0] / D_DIM;

    prep_kernel<<<9, 1024>>>(pivot, W1, b1, w2);

    const int blocks = (B + 31) / 32;
    main_kernel<<<blocks, 256>>>(r, s, pivot, b2, n_iter, out, B);
}

// round 15
// speedup vs baseline: 1.7283x; 1.5788x over previous
#include <cuda_runtime.h>
#include <cuda_fp16.h>

// Factorized ray-marching: x@W1+b1 = p1 + alpha*u.
// R15: phase B replaced by Chebyshev collocation. f(alpha)=w2@tanh(p1+alpha*u)
// is smooth in alpha; evaluate it at 8 Chebyshev nodes (independent, pipelined
// reductions), fit degree-7 poly, then run the 20-step recurrence as pure
// per-lane Horner (no shfl, no tanh-dot in the loop). Base = R11.

#define D_DIM 128
#define H_DIM 256
#define KT    8
#define NT    32
#define UPAD  264            // halves per u row
#define RPAD  136            // halves per staged r row
#define PI_F  3.14159265358979f

__device__ __half2 g_p1h2[H_DIM / 2];
__device__ __half2 g_w2h2[H_DIM / 2];
__device__ uint2   g_Bfrag[KT * NT * 32];   // 64 KB: W1 in HMMA B-fragment layout
__device__ float   g_C[64];                 // DCT matrix (with weights)
__device__ float   g_xk[8];                 // Chebyshev nodes on [-1,1]

static __device__ __forceinline__ float tanh_fast(float x) {
    float y; asm("tanh.approx.f32 %0, %1;" : "=f"(y) : "f"(x)); return y;
}
static __device__ __forceinline__ __half2 tanh2_fast(__half2 x) {
    __half2 y;
    asm("tanh.approx.f16x2 %0, %1;" : "=r"(*(unsigned*)&y) : "r"(*(unsigned*)&x));
    return y;
}
static __device__ __forceinline__ unsigned h2bits(__half2 v) { return *(unsigned*)&v; }
static __device__ __forceinline__ void mma16816(float& c0, float& c1, float& c2, float& c3,
                                                unsigned a0, unsigned a1, unsigned a2, unsigned a3,
                                                unsigned b0, unsigned b1) {
    asm volatile("mma.sync.aligned.m16n8k16.row.col.f32.f16.f16.f32 "
                 "{%0,%1,%2,%3}, {%4,%5,%6,%7}, {%8,%9}, {%0,%1,%2,%3};"
                 : "+f"(c0), "+f"(c1), "+f"(c2), "+f"(c3)
                 : "r"(a0), "r"(a1), "r"(a2), "r"(a3), "r"(b0), "r"(b1));
}

// prep (grid 9, block 1024): block 0 -> p1 + half copies + DCT matrix + nodes;
// blocks 1..8 -> W1 B-fragment packing.
__global__ __launch_bounds__(1024)
void prep_kernel(const float* __restrict__ pivot,
                 const float* __restrict__ W1,
                 const float* __restrict__ b1,
                 const float* __restrict__ w2) {
    if (blockIdx.x == 0) {
        __shared__ float red[4][H_DIM];
        __shared__ float sp1[H_DIM];
        const int j  = threadIdx.x & 255;
        const int dg = threadIdx.x >> 8;
        float s = 0.f;
        const int d0 = dg * 32;
#pragma unroll 8
        for (int d = d0; d < d0 + 32; ++d)
            s = fmaf(pivot[d], W1[(size_t)d * H_DIM + j], s);
        red[dg][j] = s;
        __syncthreads();
        if (dg == 0)
            sp1[j] = red[0][j] + red[1][j] + red[2][j] + red[3][j] + b1[j];
        __syncthreads();
        if (threadIdx.x < H_DIM / 2) {
            g_p1h2[threadIdx.x] = __floats2half2_rn(sp1[2 * threadIdx.x],
                                                    sp1[2 * threadIdx.x + 1]);
            g_w2h2[threadIdx.x] = __floats2half2_rn(w2[2 * threadIdx.x],
                                                    w2[2 * threadIdx.x + 1]);
        }
        // DCT-II matrix with quadrature weights: C[j][k] = w_j cos(j pi (k+.5)/8)
        if (threadIdx.x >= 512 && threadIdx.x < 576) {
            const int e = threadIdx.x - 512;
            const int cj = e >> 3, ck = e & 7;
            const float w = (cj == 0) ? 0.125f : 0.25f;
            g_C[e] = w * cosf((float)cj * ((float)ck + 0.5f) * (PI_F / 8.f));
        }
        if (threadIdx.x >= 576 && threadIdx.x < 584) {
            const int k = threadIdx.x - 576;
            g_xk[k] = cosf(((float)k + 0.5f) * (PI_F / 8.f));
        }
    } else {
        const int e = (blockIdx.x - 1) * 1024 + threadIdx.x;   // 0..8191
        const int tile = e >> 5;
        const int lane = e & 31;
        const int kt = tile / NT;
        const int nt = tile % NT;
        const int g = lane >> 2, t4 = lane & 3;
        const int k0 = kt * 16 + t4 * 2;
        const int col = nt * 8 + g;
        __half2 b0v = __floats2half2_rn(W1[(size_t)k0 * H_DIM + col],
                                        W1[(size_t)(k0 + 1) * H_DIM + col]);
        __half2 b1v = __floats2half2_rn(W1[(size_t)(k0 + 8) * H_DIM + col],
                                        W1[(size_t)(k0 + 9) * H_DIM + col]);
        g_Bfrag[tile * 32 + lane] = make_uint2(h2bits(b0v), h2bits(b1v));
    }
}

// ============== fused main kernel: block = 16 rows, 8 warps ==============
__global__ __launch_bounds__(256, 5)
void main_kernel(const float* __restrict__ r,
                 const float* __restrict__ s_in,
                 const float* __restrict__ pivot,
                 const float* __restrict__ b2,
                 const int* __restrict__ n_iter_ptr,
                 float* __restrict__ out,
                 int B) {
    __shared__ __half u_sh[16][UPAD];     // 8.25 KB
    __shared__ __half r_sh[16][RPAD];     // 4.25 KB
    __shared__ float  inv_sh[16];
    __shared__ float  C_sh[64];
    __shared__ float  x_sh[8];

    const int lane = threadIdx.x & 31;
    const int wib  = threadIdx.x >> 5;
    const int base_row = blockIdx.x * 16;

    // ---------- Stage 0: stage r (normalized half) + copy DCT consts ----------
    if (threadIdx.x < 64) C_sh[threadIdx.x] = g_C[threadIdx.x];
    else if (threadIdx.x < 72) x_sh[threadIdx.x - 64] = g_xk[threadIdx.x - 64];
#pragma unroll
    for (int p = 0; p < 2; ++p) {
        const int lrow = wib + p * 8;
        const int row = base_row + lrow;
        float4 v = (row < B) ? ((const float4*)(r + (size_t)row * D_DIM))[lane]
                             : make_float4(0.f, 0.f, 0.f, 0.f);
        float ss = fmaf(v.x, v.x, fmaf(v.y, v.y, fmaf(v.z, v.z, v.w * v.w)));
#pragma unroll
        for (int o = 16; o; o >>= 1) ss += __shfl_xor_sync(0xffffffffu, ss, o);
        const float inv = rsqrtf(ss);
        if (lane == 0) inv_sh[lrow] = inv;
        *(__half2*)&r_sh[lrow][lane * 4]     = __floats2half2_rn(v.x * inv, v.y * inv);
        *(__half2*)&r_sh[lrow][lane * 4 + 2] = __floats2half2_rn(v.z * inv, v.w * inv);
    }
    __syncthreads();

    // ---------- Phase A: HMMA. warp = 16 rows x 32 cols (4 n-tiles) ----------
    {
        const int ntg = wib * 4;
        const int g4 = lane >> 2, t4 = lane & 3;

        float acc[4][4];
#pragma unroll
        for (int t = 0; t < 4; ++t)
#pragma unroll
            for (int q = 0; q < 4; ++q) acc[t][q] = 0.f;

#pragma unroll
        for (int kt = 0; kt < KT; ++kt) {
            const int cbase = kt * 16 + t4 * 2;
            const unsigned a0 = *(const unsigned*)&r_sh[g4][cbase];
            const unsigned a1 = *(const unsigned*)&r_sh[g4 + 8][cbase];
            const unsigned a2 = *(const unsigned*)&r_sh[g4][cbase + 8];
            const unsigned a3 = *(const unsigned*)&r_sh[g4 + 8][cbase + 8];

            const uint2* bb = g_Bfrag + (size_t)(kt * NT + ntg) * 32 + lane;
            uint2 bf[4];
#pragma unroll
            for (int t = 0; t < 4; ++t) bf[t] = __ldg(bb + t * 32);
#pragma unroll
            for (int t = 0; t < 4; ++t)
                mma16816(acc[t][0], acc[t][1], acc[t][2], acc[t][3],
                         a0, a1, a2, a3, bf[t].x, bf[t].y);
        }

#pragma unroll
        for (int t = 0; t < 4; ++t) {
            const int col = (ntg + t) * 8 + t4 * 2;
            *(__half2*)&u_sh[g4][col]     = __floats2half2_rn(acc[t][0], acc[t][1]);
            *(__half2*)&u_sh[g4 + 8][col] = __floats2half2_rn(acc[t][2], acc[t][3]);
        }
    }
    __syncthreads();

    // ---------- Phase B: Chebyshev collocation + Horner recurrence ----------
    const int l16 = lane & 15;
    const int lrow = wib * 2 + (lane >> 4);
    const int row = base_row + lrow;
    if (row >= B) return;

    __half2 u2[8], p12[8], w22[8];
    {
        const uint4* up = (const uint4*)(&u_sh[lrow][0]) + l16 * 2;
        const uint4* pp = (const uint4*)g_p1h2 + l16 * 2;
        const uint4* wp = (const uint4*)g_w2h2 + l16 * 2;
#pragma unroll
        for (int v = 0; v < 2; ++v) {
            uint4 uu = up[v];
            uint4 aa = __ldg(pp + v), bb = __ldg(wp + v);
            u2[v * 4 + 0] = *(__half2*)&uu.x; u2[v * 4 + 1] = *(__half2*)&uu.y;
            u2[v * 4 + 2] = *(__half2*)&uu.z; u2[v * 4 + 3] = *(__half2*)&uu.w;
            p12[v * 4 + 0] = *(__half2*)&aa.x; p12[v * 4 + 1] = *(__half2*)&aa.y;
            p12[v * 4 + 2] = *(__half2*)&aa.z; p12[v * 4 + 3] = *(__half2*)&aa.w;
            w22[v * 4 + 0] = *(__half2*)&bb.x; w22[v * 4 + 1] = *(__half2*)&bb.y;
            w22[v * 4 + 2] = *(__half2*)&bb.z; w22[v * 4 + 3] = *(__half2*)&bb.w;
        }
    }

    const float b2v = b2[0];
    const int n = n_iter_ptr ? *n_iter_ptr : 20;
    const float h = (n > 0) ? 0.05f * (float)n : 1.f;   // alpha in [0, 2h]
    const float c = h;
    const float inv_h = 1.f / h;
    const __half2 h2z = __floats2half2_rn(0.f, 0.f);

    // evaluate f at 8 Chebyshev nodes (independent evaluations)
    float yk[8];
#pragma unroll
    for (int k = 0; k < 8; ++k) {
        const float ak = fmaf(h, x_sh[k], c);
        const __half2 a2h = __float2half2_rn(ak);
        __half2 s0 = h2z, s1 = h2z;
#pragma unroll
        for (int q = 0; q < 8; q += 2) {
            __half2 za = __hfma2(a2h, u2[q],     p12[q]);
            __half2 zb = __hfma2(a2h, u2[q + 1], p12[q + 1]);
            s0 = __hfma2(tanh2_fast(za), w22[q],     s0);
            s1 = __hfma2(tanh2_fast(zb), w22[q + 1], s1);
        }
        __half2 acc2 = __hadd2(s0, s1);
        yk[k] = __low2float(acc2) + __high2float(acc2);
    }
    // 8 independent 16-lane reductions, pipelined per level
#pragma unroll
    for (int o = 1; o <= 8; o <<= 1) {
#pragma unroll
        for (int k = 0; k < 8; ++k)
            yk[k] += __shfl_xor_sync(0xffffffffu, yk[k], o);
    }

    // Chebyshev coefficients a_j = sum_k C[j][k] y_k
    float a[8];
#pragma unroll
    for (int j = 0; j < 8; ++j) {
        float sj = 0.f;
#pragma unroll
        for (int k = 0; k < 8; ++k)
            sj = fmaf(C_sh[j * 8 + k], yk[k], sj);
        a[j] = sj;
    }
    // Chebyshev -> monomial (exact integer expansion of T_j)
    const float m0 = a[0] - a[2] + a[4] - a[6];
    const float m1 = a[1] - 3.f * a[3] + 5.f * a[5] - 7.f * a[7];
    const float m2 = 2.f * a[2] - 8.f * a[4] + 18.f * a[6];
    const float m3 = 4.f * a[3] - 20.f * a[5] + 56.f * a[7];
    const float m4 = 8.f * a[4] - 48.f * a[6];
    const float m5 = 16.f * a[5] - 112.f * a[7];
    const float m6 = 32.f * a[6];
    const float m7 = 64.f * a[7];

    // 20-step recurrence: pure per-lane Horner, no reductions
    float alpha = 0.f;
    for (int it = 0; it < n; ++it) {
        const float t = (alpha - c) * inv_h;
        float f = fmaf(t, m7, m6);
        f = fmaf(t, f, m5);
        f = fmaf(t, f, m4);
        f = fmaf(t, f, m3);
        f = fmaf(t, f, m2);
        f = fmaf(t, f, m1);
        f = fmaf(t, f, m0);
        alpha += 0.05f * (1.0f + tanh_fast(f + b2v));
    }

    // tail: output (lane owns dims 8*l16 .. 8*l16+7)
    const float inv_norm = inv_sh[lrow];
    const float sv = s_in[row];
    const float sig = 1.0f / (1.0f + __expf(-sv));
    const float fscale = sig * alpha * inv_norm;

    const float4* rv4 = (const float4*)(r + (size_t)row * D_DIM) + l16 * 2;
    const float4* pv4 = (const float4*)pivot + l16 * 2;
    float4* ov4 = (float4*)(out + (size_t)row * D_DIM) + l16 * 2;
#pragma unroll
    for (int j = 0; j < 2; ++j) {
        float4 rv = rv4[j];
        float4 pv = pv4[j];
        float4 o;
        o.x = fmaf(fscale, rv.x, pv.x);
        o.y = fmaf(fscale, rv.y, pv.y);
        o.z = fmaf(fscale, rv.z, pv.z);
        o.w = fmaf(fscale, rv.w, pv.w);
        ov4[j] = o;
    }
}

extern "C" void kernel_launch(void* const* d_in, const int* in_sizes, int n_in,
                              void* d_out, int out_size) {
    const float* r     = (const float*)d_in[0];   // [B,128]
    const float* s     = (const float*)d_in[1];   // [B,1]
    const float* pivot = (const float*)d_in[2];   // [128]
    const float* W1    = (const float*)d_in[3];   // [128,256]
    const float* b1    = (const float*)d_in[4];   // [256]
    const float* w2    = (const float*)d_in[5];   // [256]
    const float* b2    = (const float*)d_in[6];   // [1]
    const int* n_iter  = (n_in > 7) ? (const int*)d_in[7] : nullptr;
    float* out = (float*)d_out;

    const int B = in_sizes[0] / D_DIM;

    prep_kernel<<<9, 1024>>>(pivot, W1, b1, w2);

    const int blocks = (B + 15) / 16;
    main_kernel<<<blocks, 256>>>(r, s, pivot, b2, n_iter, out, B);
}

// round 16
// speedup vs baseline: 1.9549x; 1.1311x over previous
#include <cuda_runtime.h>
#include <cuda_fp16.h>

// Factorized ray-marching: x@W1+b1 = p1 + alpha*u.
// R16: R15 with 6 Chebyshev nodes (degree-5 fit; pole analysis shows huge
// truncation margin) and the 20-step recurrence run in beta=(alpha-c)/h
// coordinates (shorter serial chain, no per-iter remap).

#define D_DIM 128
#define H_DIM 256
#define KT    8
#define NT    32
#define NND   6              // Chebyshev nodes / poly degree-(NND-1)
#define UPAD  264            // halves per u row
#define RPAD  136            // halves per staged r row
#define PI_F  3.14159265358979f

__device__ __half2 g_p1h2[H_DIM / 2];
__device__ __half2 g_w2h2[H_DIM / 2];
__device__ uint2   g_Bfrag[KT * NT * 32];   // 64 KB: W1 in HMMA B-fragment layout
__device__ float   g_C[NND * NND];          // DCT matrix (with weights)
__device__ float   g_xk[NND];               // Chebyshev nodes on [-1,1]

static __device__ __forceinline__ float tanh_fast(float x) {
    float y; asm("tanh.approx.f32 %0, %1;" : "=f"(y) : "f"(x)); return y;
}
static __device__ __forceinline__ __half2 tanh2_fast(__half2 x) {
    __half2 y;
    asm("tanh.approx.f16x2 %0, %1;" : "=r"(*(unsigned*)&y) : "r"(*(unsigned*)&x));
    return y;
}
static __device__ __forceinline__ unsigned h2bits(__half2 v) { return *(unsigned*)&v; }
static __device__ __forceinline__ void mma16816(float& c0, float& c1, float& c2, float& c3,
                                                unsigned a0, unsigned a1, unsigned a2, unsigned a3,
                                                unsigned b0, unsigned b1) {
    asm volatile("mma.sync.aligned.m16n8k16.row.col.f32.f16.f16.f32 "
                 "{%0,%1,%2,%3}, {%4,%5,%6,%7}, {%8,%9}, {%0,%1,%2,%3};"
                 : "+f"(c0), "+f"(c1), "+f"(c2), "+f"(c3)
                 : "r"(a0), "r"(a1), "r"(a2), "r"(a3), "r"(b0), "r"(b1));
}

// prep (grid 9, block 1024): block 0 -> p1 + half copies + DCT consts;
// blocks 1..8 -> W1 B-fragment packing.
__global__ __launch_bounds__(1024)
void prep_kernel(const float* __restrict__ pivot,
                 const float* __restrict__ W1,
                 const float* __restrict__ b1,
                 const float* __restrict__ w2) {
    if (blockIdx.x == 0) {
        __shared__ float red[4][H_DIM];
        __shared__ float sp1[H_DIM];
        const int j  = threadIdx.x & 255;
        const int dg = threadIdx.x >> 8;
        float s = 0.f;
        const int d0 = dg * 32;
#pragma unroll 8
        for (int d = d0; d < d0 + 32; ++d)
            s = fmaf(pivot[d], W1[(size_t)d * H_DIM + j], s);
        red[dg][j] = s;
        __syncthreads();
        if (dg == 0)
            sp1[j] = red[0][j] + red[1][j] + red[2][j] + red[3][j] + b1[j];
        __syncthreads();
        if (threadIdx.x < H_DIM / 2) {
            g_p1h2[threadIdx.x] = __floats2half2_rn(sp1[2 * threadIdx.x],
                                                    sp1[2 * threadIdx.x + 1]);
            g_w2h2[threadIdx.x] = __floats2half2_rn(w2[2 * threadIdx.x],
                                                    w2[2 * threadIdx.x + 1]);
        }
        // DCT-II matrix with quadrature weights: C[j][k] = w_j cos(j pi (k+.5)/NND)
        if (threadIdx.x >= 512 && threadIdx.x < 512 + NND * NND) {
            const int e = threadIdx.x - 512;
            const int cj = e / NND, ck = e % NND;
            const float w = (cj == 0) ? (1.f / NND) : (2.f / NND);
            g_C[e] = w * cosf((float)cj * ((float)ck + 0.5f) * (PI_F / NND));
        }
        if (threadIdx.x >= 576 && threadIdx.x < 576 + NND) {
            const int k = threadIdx.x - 576;
            g_xk[k] = cosf(((float)k + 0.5f) * (PI_F / NND));
        }
    } else {
        const int e = (blockIdx.x - 1) * 1024 + threadIdx.x;   // 0..8191
        const int tile = e >> 5;
        const int lane = e & 31;
        const int kt = tile / NT;
        const int nt = tile % NT;
        const int g = lane >> 2, t4 = lane & 3;
        const int k0 = kt * 16 + t4 * 2;
        const int col = nt * 8 + g;
        __half2 b0v = __floats2half2_rn(W1[(size_t)k0 * H_DIM + col],
                                        W1[(size_t)(k0 + 1) * H_DIM + col]);
        __half2 b1v = __floats2half2_rn(W1[(size_t)(k0 + 8) * H_DIM + col],
                                        W1[(size_t)(k0 + 9) * H_DIM + col]);
        g_Bfrag[tile * 32 + lane] = make_uint2(h2bits(b0v), h2bits(b1v));
    }
}

// ============== fused main kernel: block = 16 rows, 8 warps ==============
__global__ __launch_bounds__(256, 5)
void main_kernel(const float* __restrict__ r,
                 const float* __restrict__ s_in,
                 const float* __restrict__ pivot,
                 const float* __restrict__ b2,
                 const int* __restrict__ n_iter_ptr,
                 float* __restrict__ out,
                 int B) {
    __shared__ __half u_sh[16][UPAD];     // 8.25 KB
    __shared__ __half r_sh[16][RPAD];     // 4.25 KB
    __shared__ float  inv_sh[16];
    __shared__ float  C_sh[NND * NND];
    __shared__ float  x_sh[NND];

    const int lane = threadIdx.x & 31;
    const int wib  = threadIdx.x >> 5;
    const int base_row = blockIdx.x * 16;

    // ---------- Stage 0: stage r (normalized half) + copy DCT consts ----------
    if (threadIdx.x < NND * NND) C_sh[threadIdx.x] = g_C[threadIdx.x];
    else if (threadIdx.x < NND * NND + NND) x_sh[threadIdx.x - NND * NND] = g_xk[threadIdx.x - NND * NND];
#pragma unroll
    for (int p = 0; p < 2; ++p) {
        const int lrow = wib + p * 8;
        const int row = base_row + lrow;
        float4 v = (row < B) ? ((const float4*)(r + (size_t)row * D_DIM))[lane]
                             : make_float4(0.f, 0.f, 0.f, 0.f);
        float ss = fmaf(v.x, v.x, fmaf(v.y, v.y, fmaf(v.z, v.z, v.w * v.w)));
#pragma unroll
        for (int o = 16; o; o >>= 1) ss += __shfl_xor_sync(0xffffffffu, ss, o);
        const float inv = rsqrtf(ss);
        if (lane == 0) inv_sh[lrow] = inv;
        *(__half2*)&r_sh[lrow][lane * 4]     = __floats2half2_rn(v.x * inv, v.y * inv);
        *(__half2*)&r_sh[lrow][lane * 4 + 2] = __floats2half2_rn(v.z * inv, v.w * inv);
    }
    __syncthreads();

    // ---------- Phase A: HMMA. warp = 16 rows x 32 cols (4 n-tiles) ----------
    {
        const int ntg = wib * 4;
        const int g4 = lane >> 2, t4 = lane & 3;

        float acc[4][4];
#pragma unroll
        for (int t = 0; t < 4; ++t)
#pragma unroll
            for (int q = 0; q < 4; ++q) acc[t][q] = 0.f;

#pragma unroll
        for (int kt = 0; kt < KT; ++kt) {
            const int cbase = kt * 16 + t4 * 2;
            const unsigned a0 = *(const unsigned*)&r_sh[g4][cbase];
            const unsigned a1 = *(const unsigned*)&r_sh[g4 + 8][cbase];
            const unsigned a2 = *(const unsigned*)&r_sh[g4][cbase + 8];
            const unsigned a3 = *(const unsigned*)&r_sh[g4 + 8][cbase + 8];

            const uint2* bb = g_Bfrag + (size_t)(kt * NT + ntg) * 32 + lane;
            uint2 bf[4];
#pragma unroll
            for (int t = 0; t < 4; ++t) bf[t] = __ldg(bb + t * 32);
#pragma unroll
            for (int t = 0; t < 4; ++t)
                mma16816(acc[t][0], acc[t][1], acc[t][2], acc[t][3],
                         a0, a1, a2, a3, bf[t].x, bf[t].y);
        }

#pragma unroll
        for (int t = 0; t < 4; ++t) {
            const int col = (ntg + t) * 8 + t4 * 2;
            *(__half2*)&u_sh[g4][col]     = __floats2half2_rn(acc[t][0], acc[t][1]);
            *(__half2*)&u_sh[g4 + 8][col] = __floats2half2_rn(acc[t][2], acc[t][3]);
        }
    }
    __syncthreads();

    // ---------- Phase B: 6-node Chebyshev collocation + beta-Horner ----------
    const int l16 = lane & 15;
    const int lrow = wib * 2 + (lane >> 4);
    const int row = base_row + lrow;
    if (row >= B) return;

    __half2 u2[8], p12[8], w22[8];
    {
        const uint4* up = (const uint4*)(&u_sh[lrow][0]) + l16 * 2;
        const uint4* pp = (const uint4*)g_p1h2 + l16 * 2;
        const uint4* wp = (const uint4*)g_w2h2 + l16 * 2;
#pragma unroll
        for (int v = 0; v < 2; ++v) {
            uint4 uu = up[v];
            uint4 aa = __ldg(pp + v), bb = __ldg(wp + v);
            u2[v * 4 + 0] = *(__half2*)&uu.x; u2[v * 4 + 1] = *(__half2*)&uu.y;
            u2[v * 4 + 2] = *(__half2*)&uu.z; u2[v * 4 + 3] = *(__half2*)&uu.w;
            p12[v * 4 + 0] = *(__half2*)&aa.x; p12[v * 4 + 1] = *(__half2*)&aa.y;
            p12[v * 4 + 2] = *(__half2*)&aa.z; p12[v * 4 + 3] = *(__half2*)&aa.w;
            w22[v * 4 + 0] = *(__half2*)&bb.x; w22[v * 4 + 1] = *(__half2*)&bb.y;
            w22[v * 4 + 2] = *(__half2*)&bb.z; w22[v * 4 + 3] = *(__half2*)&bb.w;
        }
    }

    const float b2v = b2[0];
    const int n = n_iter_ptr ? *n_iter_ptr : 20;
    const float h = (n > 0) ? 0.05f * (float)n : 1.f;   // alpha in [0, 2h]
    const float c = h;
    const float step = 0.05f / h;                        // beta step scale
    const __half2 h2z = __floats2half2_rn(0.f, 0.f);

    // evaluate f at NND Chebyshev nodes (independent evaluations)
    float yk[NND];
#pragma unroll
    for (int k = 0; k < NND; ++k) {
        const float ak = fmaf(h, x_sh[k], c);
        const __half2 a2h = __float2half2_rn(ak);
        __half2 s0 = h2z, s1 = h2z;
#pragma unroll
        for (int q = 0; q < 8; q += 2) {
            __half2 za = __hfma2(a2h, u2[q],     p12[q]);
            __half2 zb = __hfma2(a2h, u2[q + 1], p12[q + 1]);
            s0 = __hfma2(tanh2_fast(za), w22[q],     s0);
            s1 = __hfma2(tanh2_fast(zb), w22[q + 1], s1);
        }
        __half2 acc2 = __hadd2(s0, s1);
        yk[k] = __low2float(acc2) + __high2float(acc2);
    }
    // NND independent 16-lane reductions, pipelined per level
#pragma unroll
    for (int o = 1; o <= 8; o <<= 1) {
#pragma unroll
        for (int k = 0; k < NND; ++k)
            yk[k] += __shfl_xor_sync(0xffffffffu, yk[k], o);
    }

    // Chebyshev coefficients a_j = sum_k C[j][k] y_k
    float a[NND];
#pragma unroll
    for (int j = 0; j < NND; ++j) {
        float sj = 0.f;
#pragma unroll
        for (int k = 0; k < NND; ++k)
            sj = fmaf(C_sh[j * NND + k], yk[k], sj);
        a[j] = sj;
    }
    // Chebyshev -> monomial (degree 5, exact integer expansion)
    const float m0 = a[0] - a[2] + a[4];
    const float m1 = a[1] - 3.f * a[3] + 5.f * a[5];
    const float m2 = 2.f * a[2] - 8.f * a[4];
    const float m3 = 4.f * a[3] - 20.f * a[5];
    const float m4 = 8.f * a[4];
    const float m5 = 16.f * a[5];

    // 20-step recurrence in beta = (alpha - c)/h: pure per-lane Horner
    float beta = -1.f;          // alpha = 0
    for (int it = 0; it < n; ++it) {
        float f = fmaf(beta, m5, m4);
        f = fmaf(beta, f, m3);
        f = fmaf(beta, f, m2);
        f = fmaf(beta, f, m1);
        f = fmaf(beta, f, m0);
        beta += step * (1.0f + tanh_fast(f + b2v));
    }
    const float alpha = fmaf(h, beta, c);

    // tail: output (lane owns dims 8*l16 .. 8*l16+7)
    const float inv_norm = inv_sh[lrow];
    const float sv = s_in[row];
    const float sig = 1.0f / (1.0f + __expf(-sv));
    const float fscale = sig * alpha * inv_norm;

    const float4* rv4 = (const float4*)(r + (size_t)row * D_DIM) + l16 * 2;
    const float4* pv4 = (const float4*)pivot + l16 * 2;
    float4* ov4 = (float4*)(out + (size_t)row * D_DIM) + l16 * 2;
#pragma unroll
    for (int j = 0; j < 2; ++j) {
        float4 rv = rv4[j];
        float4 pv = pv4[j];
        float4 o;
        o.x = fmaf(fscale, rv.x, pv.x);
        o.y = fmaf(fscale, rv.y, pv.y);
        o.z = fmaf(fscale, rv.z, pv.z);
        o.w = fmaf(fscale, rv.w, pv.w);
        ov4[j] = o;
    }
}

extern "C" void kernel_launch(void* const* d_in, const int* in_sizes, int n_in,
                              void* d_out, int out_size) {
    const float* r     = (const float*)d_in[0];   // [B,128]
    const float* s     = (const float*)d_in[1];   // [B,1]
    const float* pivot = (const float*)d_in[2];   // [128]
    const float* W1    = (const float*)d_in[3];   // [128,256]
    const float* b1    = (const float*)d_in[4];   // [256]
    const float* w2    = (const float*)d_in[5];   // [256]
    const float* b2    = (const float*)d_in[6];   // [1]
    const int* n_iter  = (n_in > 7) ? (const int*)d_in[7] : nullptr;
    float* out = (float*)d_out;

    const int B = in_sizes[0] / D_DIM;

    prep_kernel<<<9, 1024>>>(pivot, W1, b1, w2);

    const int blocks = (B + 15) / 16;
    main_kernel<<<blocks, 256>>>(r, s, pivot, b2, n_iter, out, B);
}